// round 1
// baseline (speedup 1.0000x reference)
#include <cuda_runtime.h>
#include <cuda_bf16.h>

// ---------------------------------------------------------------------------
// RIMDLoss fused kernel.
// total = recon + 0.1*lap + 0.01*drift + 0.1*arap + beta*kl
//   recon = mean((pred-target)^2)                       [node pass]
//   lap   = sum(|p_i - p_j|^2)/E                        [edge pass]
//   arap  = var(len, ddof=1), len=|p_i-p_j|; len^2=d2   [edge pass, reuses lap sum]
//   drift = sum_g |mean_g(pred)|^2 / G                  [node pass, warp-agg atomics]
//   kl    = mean_g(-0.5*sum(1+lv-mu^2-exp(lv)))         [final pass]
//   beta  = epoch<10 ? epoch/10 : 1
// ---------------------------------------------------------------------------

#define NUM_GRAPHS 64

__device__ double g_recon;   // sum (p-t)^2 over N*2 elems
__device__ double g_lap;     // sum d2 over edges  (== sum len^2)
__device__ double g_len;     // sum len over edges
__device__ float  g_sumx[NUM_GRAPHS];
__device__ float  g_sumy[NUM_GRAPHS];
__device__ float  g_cnt [NUM_GRAPHS];

__global__ void init_kernel() {
    int t = threadIdx.x;
    if (t == 0) { g_recon = 0.0; g_lap = 0.0; g_len = 0.0; }
    if (t < NUM_GRAPHS) { g_sumx[t] = 0.f; g_sumy[t] = 0.f; g_cnt[t] = 0.f; }
}

__device__ __forceinline__ float warpReduceF(float v) {
    #pragma unroll
    for (int o = 16; o; o >>= 1) v += __shfl_down_sync(0xffffffffu, v, o);
    return v;
}
__device__ __forceinline__ double warpReduceD(double v) {
    #pragma unroll
    for (int o = 16; o; o >>= 1) v += __shfl_down_sync(0xffffffffu, v, o);
    return v;
}

// Block-reduce a double and atomically add into *dst (thread 0 of block).
__device__ __forceinline__ void blockAtomicAddD(double v, double* dst, double* sh) {
    int lane = threadIdx.x & 31;
    int wid  = threadIdx.x >> 5;
    v = warpReduceD(v);
    if (lane == 0) sh[wid] = v;
    __syncthreads();
    int nw = (blockDim.x + 31) >> 5;
    if (wid == 0) {
        double x = (lane < nw) ? sh[lane] : 0.0;
        x = warpReduceD(x);
        if (lane == 0) atomicAdd(dst, x);
    }
    __syncthreads();
}

// ---------------------------------------------------------------------------
// Node pass: recon partial sums + per-graph (sum, count) with warp-aggregated
// atomics (batch_indices is sorted -> warps are almost always graph-uniform).
// ---------------------------------------------------------------------------
__global__ void node_kernel(const float2* __restrict__ pred,
                            const float2* __restrict__ targ,
                            const int*    __restrict__ batch,
                            int N) {
    __shared__ double sh[32];
    int lane   = threadIdx.x & 31;
    int gwid   = (blockIdx.x * blockDim.x + threadIdx.x) >> 5;
    int nwarps = (gridDim.x * blockDim.x) >> 5;

    float racc = 0.f;
    for (long long base = (long long)gwid * 32; base < N; base += (long long)nwarps * 32) {
        int idx   = (int)base + lane;
        bool valid = idx < N;
        float2 p = valid ? pred[idx] : make_float2(0.f, 0.f);
        if (valid) {
            float2 t = targ[idx];
            float dx = p.x - t.x, dy = p.y - t.y;
            racc += dx * dx + dy * dy;
        }
        int g  = valid ? batch[idx] : -1;
        int g0 = __shfl_sync(0xffffffffu, g, 0);   // lane 0 always valid when any lane is
        unsigned vm = __ballot_sync(0xffffffffu, valid);
        bool uniform = __all_sync(0xffffffffu, (!valid) || (g == g0));
        if (uniform) {
            float sx = warpReduceF(valid ? p.x : 0.f);
            float sy = warpReduceF(valid ? p.y : 0.f);
            if (lane == 0 && vm) {
                atomicAdd(&g_sumx[g0], sx);
                atomicAdd(&g_sumy[g0], sy);
                atomicAdd(&g_cnt [g0], (float)__popc(vm));
            }
        } else if (valid) {   // rare: warps straddling a graph boundary
            atomicAdd(&g_sumx[g], p.x);
            atomicAdd(&g_sumy[g], p.y);
            atomicAdd(&g_cnt [g], 1.f);
        }
    }
    blockAtomicAddD((double)racc, &g_recon, sh);
}

// ---------------------------------------------------------------------------
// Edge pass: vectorized int4 index reads, random float2 gathers (L2-resident).
// Accumulate sum(d2) and sum(len); note len^2 == d2 so no third accumulator.
// ---------------------------------------------------------------------------
__global__ void edge_kernel(const float2* __restrict__ pred,
                            const int*    __restrict__ ei,  // edge_index row 0
                            int E) {
    __shared__ double sh2[32];
    __shared__ double shl[32];
    const int* ej = ei + E;

    int tid    = blockIdx.x * blockDim.x + threadIdx.x;
    int stride = gridDim.x * blockDim.x;

    float s2 = 0.f, sl = 0.f;

    int E4 = E >> 2;
    const int4* ei4 = (const int4*)ei;
    const int4* ej4 = (const int4*)ej;

    for (int k = tid; k < E4; k += stride) {
        int4 a = ei4[k];
        int4 b = ej4[k];
        float2 pa0 = __ldg(&pred[a.x]); float2 pb0 = __ldg(&pred[b.x]);
        float2 pa1 = __ldg(&pred[a.y]); float2 pb1 = __ldg(&pred[b.y]);
        float2 pa2 = __ldg(&pred[a.z]); float2 pb2 = __ldg(&pred[b.z]);
        float2 pa3 = __ldg(&pred[a.w]); float2 pb3 = __ldg(&pred[b.w]);

        float dx0 = pa0.x - pb0.x, dy0 = pa0.y - pb0.y;
        float dx1 = pa1.x - pb1.x, dy1 = pa1.y - pb1.y;
        float dx2 = pa2.x - pb2.x, dy2 = pa2.y - pb2.y;
        float dx3 = pa3.x - pb3.x, dy3 = pa3.y - pb3.y;

        float d0 = dx0 * dx0 + dy0 * dy0;
        float d1 = dx1 * dx1 + dy1 * dy1;
        float d2 = dx2 * dx2 + dy2 * dy2;
        float d3 = dx3 * dx3 + dy3 * dy3;

        s2 += (d0 + d1) + (d2 + d3);
        sl += (sqrtf(d0) + sqrtf(d1)) + (sqrtf(d2) + sqrtf(d3));
    }
    // scalar tail (E % 4)
    for (int k = (E4 << 2) + tid; k < E; k += stride) {
        float2 pa = __ldg(&pred[ei[k]]);
        float2 pb = __ldg(&pred[ej[k]]);
        float dx = pa.x - pb.x, dy = pa.y - pb.y;
        float d = dx * dx + dy * dy;
        s2 += d;
        sl += sqrtf(d);
    }

    blockAtomicAddD((double)s2, &g_lap, sh2);
    blockAtomicAddD((double)sl, &g_len, shl);
}

// ---------------------------------------------------------------------------
// Final pass: KL + compose scalar.
// ---------------------------------------------------------------------------
__global__ void final_kernel(const float* __restrict__ mu,
                             const float* __restrict__ logvar,
                             const int*   __restrict__ epoch_ptr,
                             float* __restrict__ out,
                             int GL, int E, int N) {
    __shared__ double sh[32];
    double kacc = 0.0;
    for (int i = threadIdx.x; i < GL; i += blockDim.x) {
        float lv = logvar[i];
        float m  = mu[i];
        kacc += (double)(1.0f + lv - m * m - expf(lv));
    }
    // block reduce kacc
    int lane = threadIdx.x & 31;
    int wid  = threadIdx.x >> 5;
    kacc = warpReduceD(kacc);
    if (lane == 0) sh[wid] = kacc;
    __syncthreads();

    if (threadIdx.x == 0) {
        double ktot = 0.0;
        int nw = (blockDim.x + 31) >> 5;
        for (int w = 0; w < nw; w++) ktot += sh[w];
        double kl = -0.5 * ktot / (double)NUM_GRAPHS;

        double drift = 0.0;
        #pragma unroll
        for (int g = 0; g < NUM_GRAPHS; g++) {
            double c  = (double)g_cnt[g];
            double mx = (double)g_sumx[g] / c;
            double my = (double)g_sumy[g] / c;
            drift += mx * mx + my * my;
        }
        drift /= (double)NUM_GRAPHS;

        double recon = g_recon / (2.0 * (double)N);
        double lap   = g_lap / (double)E;
        double var   = (g_lap - g_len * g_len / (double)E) / ((double)E - 1.0);

        int epoch = epoch_ptr ? *epoch_ptr : 5;
        double beta = (epoch < 10) ? ((double)epoch / 10.0) : 1.0;

        out[0] = (float)(recon + 0.1 * lap + 0.01 * drift + 0.1 * var + beta * kl);
    }
}

// ---------------------------------------------------------------------------
extern "C" void kernel_launch(void* const* d_in, const int* in_sizes, int n_in,
                              void* d_out, int out_size) {
    const float2* pred   = (const float2*)d_in[0];
    const float2* targ   = (const float2*)d_in[1];
    const int*    eidx   = (const int*)   d_in[2];
    const int*    batch  = (const int*)   d_in[3];
    const float*  mu     = (const float*) d_in[4];
    const float*  logvar = (const float*) d_in[5];
    const int*    epoch  = (n_in >= 7) ? (const int*)d_in[6] : nullptr;
    float*        out    = (float*)d_out;

    int N  = in_sizes[0] / 2;       // nodes
    int E  = in_sizes[2] / 2;       // edges
    int GL = in_sizes[4];           // NUM_GRAPHS * LATENT

    init_kernel<<<1, 64>>>();

    {
        int threads = 256;
        int blocks  = (N + threads - 1) / threads;
        if (blocks > 1024) blocks = 1024;
        node_kernel<<<blocks, threads>>>(pred, targ, batch, N);
    }
    {
        int threads = 256;
        int groups  = (E >> 2) > 0 ? (E >> 2) : E;
        int blocks  = (groups + threads - 1) / threads;
        if (blocks > 1184) blocks = 1184;   // 148 SMs * 8 blocks
        edge_kernel<<<blocks, threads>>>(pred, eidx, E);
    }
    final_kernel<<<1, 256>>>(mu, logvar, epoch, out, GL, E, N);
}

// round 4
// speedup vs baseline: 1.5098x; 1.5098x over previous
#include <cuda_runtime.h>
#include <cuda_bf16.h>

// ---------------------------------------------------------------------------
// RIMDLoss fused loss.
// total = recon + 0.1*lap + 0.01*drift + 0.1*arap + beta*kl
// R1 lesson: final composition kernel was 92us due to serial fp64 division
// chains in thread 0. This round: float math, parallel drift, __ldcs on the
// single-use streams (edge_index, target, batch) to protect pred's L2
// residency for the random gathers.
// R2 was an infra failure (container died twice); this is the same design.
// ---------------------------------------------------------------------------

#define NUM_GRAPHS 64

__device__ double g_recon;   // sum (p-t)^2 over all elements
__device__ double g_lap;     // sum d2 over edges  (== sum len^2)
__device__ double g_len;     // sum len over edges
__device__ float  g_sumx[NUM_GRAPHS];
__device__ float  g_sumy[NUM_GRAPHS];
__device__ float  g_cnt [NUM_GRAPHS];

__global__ void init_kernel() {
    int t = threadIdx.x;
    if (t == 0) { g_recon = 0.0; g_lap = 0.0; g_len = 0.0; }
    if (t < NUM_GRAPHS) { g_sumx[t] = 0.f; g_sumy[t] = 0.f; g_cnt[t] = 0.f; }
}

__device__ __forceinline__ float warpReduceF(float v) {
    #pragma unroll
    for (int o = 16; o; o >>= 1) v += __shfl_down_sync(0xffffffffu, v, o);
    return v;
}
__device__ __forceinline__ double warpReduceD(double v) {
    #pragma unroll
    for (int o = 16; o; o >>= 1) v += __shfl_down_sync(0xffffffffu, v, o);
    return v;
}

// Block-reduce a double and atomically add into *dst.
__device__ __forceinline__ void blockAtomicAddD(double v, double* dst, double* sh) {
    int lane = threadIdx.x & 31;
    int wid  = threadIdx.x >> 5;
    v = warpReduceD(v);
    if (lane == 0) sh[wid] = v;
    __syncthreads();
    int nw = (blockDim.x + 31) >> 5;
    if (wid == 0) {
        double x = (lane < nw) ? sh[lane] : 0.0;
        x = warpReduceD(x);
        if (lane == 0) atomicAdd(dst, x);
    }
    __syncthreads();
}

// ---------------------------------------------------------------------------
// Node pass: recon partials + per-graph (sum, count) with warp-aggregated
// atomics (batch_indices is sorted -> warps are almost always graph-uniform).
// pred uses default caching (we WANT it resident in L2 for the edge pass);
// targ/batch are single-use -> evict-first.
// ---------------------------------------------------------------------------
__global__ void node_kernel(const float2* __restrict__ pred,
                            const float2* __restrict__ targ,
                            const int*    __restrict__ batch,
                            int N) {
    __shared__ double sh[32];
    int lane   = threadIdx.x & 31;
    int gwid   = (blockIdx.x * blockDim.x + threadIdx.x) >> 5;
    int nwarps = (gridDim.x * blockDim.x) >> 5;

    float racc = 0.f;
    for (long long base = (long long)gwid * 32; base < N; base += (long long)nwarps * 32) {
        int idx   = (int)base + lane;
        bool valid = idx < N;
        float2 p = valid ? pred[idx] : make_float2(0.f, 0.f);
        if (valid) {
            float2 t = __ldcs(&targ[idx]);
            float dx = p.x - t.x, dy = p.y - t.y;
            racc += dx * dx + dy * dy;
        }
        int g  = valid ? __ldcs(&batch[idx]) : -1;
        int g0 = __shfl_sync(0xffffffffu, g, 0);
        unsigned vm = __ballot_sync(0xffffffffu, valid);
        bool uniform = __all_sync(0xffffffffu, (!valid) || (g == g0));
        if (uniform) {
            float sx = warpReduceF(valid ? p.x : 0.f);
            float sy = warpReduceF(valid ? p.y : 0.f);
            if (lane == 0 && vm) {
                atomicAdd(&g_sumx[g0], sx);
                atomicAdd(&g_sumy[g0], sy);
                atomicAdd(&g_cnt [g0], (float)__popc(vm));
            }
        } else if (valid) {   // rare: warp straddles a graph boundary
            atomicAdd(&g_sumx[g], p.x);
            atomicAdd(&g_sumy[g], p.y);
            atomicAdd(&g_cnt [g], 1.f);
        }
    }
    blockAtomicAddD((double)racc, &g_recon, sh);
}

// ---------------------------------------------------------------------------
// Edge pass: int4 index reads with evict-first hint (128MB single-use stream
// must not thrash pred's 8MB L2 working set); random float2 gathers
// (L2-resident). len^2 == d2, so one accumulator serves both Laplacian and
// ARAP's second moment.
// ---------------------------------------------------------------------------
__global__ void edge_kernel(const float2* __restrict__ pred,
                            const int*    __restrict__ ei,  // row 0; row 1 at ei+E
                            int E) {
    __shared__ double sh2[32];
    __shared__ double shl[32];
    const int* ej = ei + E;

    int tid    = blockIdx.x * blockDim.x + threadIdx.x;
    int stride = gridDim.x * blockDim.x;

    float s2 = 0.f, sl = 0.f;

    int E4 = E >> 2;
    const int4* ei4 = (const int4*)ei;
    const int4* ej4 = (const int4*)ej;

    for (int k = tid; k < E4; k += stride) {
        int4 a = __ldcs(&ei4[k]);
        int4 b = __ldcs(&ej4[k]);
        float2 pa0 = __ldg(&pred[a.x]); float2 pb0 = __ldg(&pred[b.x]);
        float2 pa1 = __ldg(&pred[a.y]); float2 pb1 = __ldg(&pred[b.y]);
        float2 pa2 = __ldg(&pred[a.z]); float2 pb2 = __ldg(&pred[b.z]);
        float2 pa3 = __ldg(&pred[a.w]); float2 pb3 = __ldg(&pred[b.w]);

        float dx0 = pa0.x - pb0.x, dy0 = pa0.y - pb0.y;
        float dx1 = pa1.x - pb1.x, dy1 = pa1.y - pb1.y;
        float dx2 = pa2.x - pb2.x, dy2 = pa2.y - pb2.y;
        float dx3 = pa3.x - pb3.x, dy3 = pa3.y - pb3.y;

        float d0 = dx0 * dx0 + dy0 * dy0;
        float d1 = dx1 * dx1 + dy1 * dy1;
        float d2 = dx2 * dx2 + dy2 * dy2;
        float d3 = dx3 * dx3 + dy3 * dy3;

        s2 += (d0 + d1) + (d2 + d3);
        sl += (sqrtf(d0) + sqrtf(d1)) + (sqrtf(d2) + sqrtf(d3));
    }
    for (int k = (E4 << 2) + tid; k < E; k += stride) {   // tail (E % 4)
        float2 pa = __ldg(&pred[__ldcs(&ei[k])]);
        float2 pb = __ldg(&pred[__ldcs(&ej[k])]);
        float dx = pa.x - pb.x, dy = pa.y - pb.y;
        float d = dx * dx + dy * dy;
        s2 += d;
        sl += sqrtf(d);
    }

    blockAtomicAddD((double)s2, &g_lap, sh2);
    blockAtomicAddD((double)sl, &g_len, shl);
}

// ---------------------------------------------------------------------------
// Final pass: KL (float, parallel) + drift (float divides, parallel) +
// composition. NO fp64 division chains (R1's 92us bug).
// ---------------------------------------------------------------------------
__global__ void final_kernel(const float* __restrict__ mu,
                             const float* __restrict__ logvar,
                             const int*   __restrict__ epoch_ptr,
                             float* __restrict__ out,
                             int GL, int E, int N) {
    __shared__ float shk[8];     // per-warp KL partials (256 thr = 8 warps)
    __shared__ float shd[2];     // drift partials (2 warps cover 64 graphs)

    int lane = threadIdx.x & 31;
    int wid  = threadIdx.x >> 5;

    // KL partials in float (values O(1), GL=8192 -> float sum is plenty)
    float kacc = 0.f;
    for (int i = threadIdx.x; i < GL; i += blockDim.x) {
        float lv = logvar[i];
        float m  = mu[i];
        kacc += 1.0f + lv - m * m - __expf(lv);
    }
    kacc = warpReduceF(kacc);
    if (lane == 0) shk[wid] = kacc;

    // Drift: one graph per thread (threads 0..63), float division (cheap)
    if (threadIdx.x < NUM_GRAPHS) {
        int g = threadIdx.x;
        float inv = 1.0f / g_cnt[g];
        float mx = g_sumx[g] * inv;
        float my = g_sumy[g] * inv;
        float d  = mx * mx + my * my;
        d = warpReduceF(d);
        if (lane == 0) shd[wid] = d;
    }
    __syncthreads();

    if (threadIdx.x == 0) {
        float ktot = 0.f;
        #pragma unroll
        for (int w = 0; w < 8; w++) ktot += shk[w];
        float kl = -0.5f * ktot / (float)NUM_GRAPHS;

        float drift = (shd[0] + shd[1]) / (float)NUM_GRAPHS;

        // accumulators are exact-ish doubles; compose in float (rel tol 1e-3)
        float S2 = (float)g_lap;
        float S1 = (float)g_len;
        float fE = (float)E;
        float recon = (float)g_recon / (2.0f * (float)N);
        float lap   = S2 / fE;
        float var   = (S2 - S1 * (S1 / fE)) / (fE - 1.0f);

        int epoch = epoch_ptr ? *epoch_ptr : 5;
        float beta = (epoch < 10) ? ((float)epoch * 0.1f) : 1.0f;

        out[0] = recon + 0.1f * lap + 0.01f * drift + 0.1f * var + beta * kl;
    }
}

// ---------------------------------------------------------------------------
extern "C" void kernel_launch(void* const* d_in, const int* in_sizes, int n_in,
                              void* d_out, int out_size) {
    const float2* pred   = (const float2*)d_in[0];
    const float2* targ   = (const float2*)d_in[1];
    const int*    eidx   = (const int*)   d_in[2];
    const int*    batch  = (const int*)   d_in[3];
    const float*  mu     = (const float*) d_in[4];
    const float*  logvar = (const float*) d_in[5];
    const int*    epoch  = (n_in >= 7) ? (const int*)d_in[6] : nullptr;
    float*        out    = (float*)d_out;

    int N  = in_sizes[0] / 2;       // nodes
    int E  = in_sizes[2] / 2;       // edges
    int GL = in_sizes[4];           // NUM_GRAPHS * LATENT

    init_kernel<<<1, 64>>>();

    {
        int threads = 256;
        int blocks  = (N + threads - 1) / threads;
        if (blocks < 1) blocks = 1;
        if (blocks > 1184) blocks = 1184;
        node_kernel<<<blocks, threads>>>(pred, targ, batch, N);
    }
    {
        int threads = 256;
        int groups  = (E >> 2) > 0 ? (E >> 2) : 1;
        int blocks  = (groups + threads - 1) / threads;
        if (blocks < 1) blocks = 1;
        if (blocks > 1184) blocks = 1184;   // 148 SMs * 8 blocks = one wave
        edge_kernel<<<blocks, threads>>>(pred, eidx, E);
    }
    final_kernel<<<1, 256>>>(mu, logvar, epoch, out, GL, E, N);
}